// round 13
// baseline (speedup 1.0000x reference)
#include <cuda_runtime.h>
#include <math.h>
#include <float.h>

#define Bq 4
#define Sq 1024
#define Nk 16384
#define KK 16
#define G  16
#define NC (G * G * G)   // 4096 cells
#define TPQ8 8           // threads per query in knn
#define QPB3 32          // queries per CTA in knn

typedef unsigned long long ull;

// ---------------- scratch (device globals; no allocation allowed) ----------------
__device__ float g_cswq[128];
__device__ float g_cswk[128];
__device__ float g_csw2[128];
__device__ float g_consts[4];           // [0]=sum_bq, [1]=sum_bk, [2]=sum_b2
__device__ float g_qsum[Bq * Sq];
__device__ float g_ksum[Bq * Nk];
__device__ float g_attn[Bq * Sq * KK];
__device__ int   g_nidx[Bq * Sq * KK];
__device__ float g_acol[Bq * KK];
__device__ int    g_cellStart[Bq][NC + 1];
__device__ int    g_cellCur[Bq][NC];    // histogram, then running scatter offsets
__device__ float4 g_spos4[Bq * Nk];     // cell-sorted (x,y,z,kk)
__device__ int    g_sidx[Bq * Nk];      // original indices
__device__ int    g_qCur[Bq][NC];       // query histogram / running offsets
__device__ int    g_qord[Bq * Sq];      // cell-sorted query ids (per batch)

#define PERM(n) ((unsigned)((((n) & 511) << 5) | ((unsigned)(n) >> 9)))

__device__ __forceinline__ int cell_of(float v) {
    int c = (int)(v * (float)G);
    return c < 0 ? 0 : (c > G - 1 ? G - 1 : c);
}

// ---------------- prep: column sums of Wq/Wk/W2, bias sums ----------------
__global__ void prep_kernel(const float* __restrict__ Wq, const float* __restrict__ bq,
                            const float* __restrict__ Wk, const float* __restrict__ bk,
                            const float* __restrict__ W2, const float* __restrict__ b2) {
    int i = threadIdx.x;  // 128 threads
    float sq = 0.f, sk = 0.f, s2 = 0.f;
    for (int o = 0; o < 128; o++) {
        sq += Wq[o * 128 + i];
        sk += Wk[o * 128 + i];
        s2 += W2[o * 128 + i];
    }
    g_cswq[i] = sq;
    g_cswk[i] = sk;
    g_csw2[i] = s2;

    float vq = bq[i], vk = bk[i], v2 = b2[i];
    #pragma unroll
    for (int o = 16; o; o >>= 1) {
        vq += __shfl_xor_sync(0xffffffffu, vq, o);
        vk += __shfl_xor_sync(0xffffffffu, vk, o);
        v2 += __shfl_xor_sync(0xffffffffu, v2, o);
    }
    __shared__ float rb[3][4];
    if ((i & 31) == 0) {
        rb[0][i >> 5] = vq; rb[1][i >> 5] = vk; rb[2][i >> 5] = v2;
    }
    __syncthreads();
    if (i == 0) {
        g_consts[0] = rb[0][0] + rb[0][1] + rb[0][2] + rb[0][3];
        g_consts[1] = rb[1][0] + rb[1][1] + rb[1][2] + rb[1][3];
        g_consts[2] = rb[2][0] + rb[2][1] + rb[2][2] + rb[2][3];
    }
}

// ---------------- grid build ----------------
__global__ __launch_bounds__(256) void zero_kernel() {
    int i = blockIdx.x * 256 + threadIdx.x;       // 0 .. 2*Bq*NC-1
    if (i < Bq * NC) ((int*)g_cellCur)[i] = 0;
    else             ((int*)g_qCur)[i - Bq * NC] = 0;
}

__global__ __launch_bounds__(256) void count_kernel(const float* __restrict__ k_pos) {
    int idx = blockIdx.x * 256 + threadIdx.x;     // 0 .. Bq*Nk-1
    int b = idx >> 14;
    const float* kp = k_pos + (size_t)idx * 3;
    int cx = cell_of(kp[0]), cy = cell_of(kp[1]), cz = cell_of(kp[2]);
    atomicAdd(&g_cellCur[b][(cz * G + cy) * G + cx], 1);
}

__global__ __launch_bounds__(256) void countq_kernel(const float* __restrict__ q_pos) {
    int idx = blockIdx.x * 256 + threadIdx.x;     // 0 .. Bq*Sq-1
    int b = idx >> 10;
    const float* qp = q_pos + (size_t)idx * 3;
    int cx = cell_of(qp[0]), cy = cell_of(qp[1]), cz = cell_of(qp[2]);
    atomicAdd(&g_qCur[b][(cz * G + cy) * G + cx], 1);
}

// blockIdx.x in [0, 2*Bq): first Bq -> point grid (also writes cellStart),
// last Bq -> query grid (running offsets only).
__global__ __launch_bounds__(1024) void scan_kernel() {
    int bb = blockIdx.x, t = threadIdx.x;
    int isQ = bb >= Bq;
    int b = isQ ? bb - Bq : bb;
    int* cur = isQ ? g_qCur[b] : g_cellCur[b];
    __shared__ int part[1024];
    int base = t * 4;
    int c0 = cur[base], c1 = cur[base + 1], c2 = cur[base + 2], c3 = cur[base + 3];
    int s = c0 + c1 + c2 + c3;
    part[t] = s;
    __syncthreads();
    for (int o = 1; o < 1024; o <<= 1) {
        int v = (t >= o) ? part[t - o] : 0;
        __syncthreads();
        part[t] += v;
        __syncthreads();
    }
    int run = part[t] - s;
    if (!isQ) {
        g_cellStart[b][base] = run;     cur[base] = run;     run += c0;
        g_cellStart[b][base + 1] = run; cur[base + 1] = run; run += c1;
        g_cellStart[b][base + 2] = run; cur[base + 2] = run; run += c2;
        g_cellStart[b][base + 3] = run; cur[base + 3] = run; run += c3;
        if (t == 1023) g_cellStart[b][NC] = run;
    } else {
        cur[base] = run;     run += c0;
        cur[base + 1] = run; run += c1;
        cur[base + 2] = run; run += c2;
        cur[base + 3] = run;
    }
}

__global__ __launch_bounds__(256) void scatter_kernel(const float* __restrict__ k_pos) {
    int idx = blockIdx.x * 256 + threadIdx.x;     // 0 .. Bq*Nk-1
    int b = idx >> 14, n = idx & (Nk - 1);
    const float* kp = k_pos + (size_t)idx * 3;
    float x = kp[0], y = kp[1], z = kp[2];
    float kk = x * x + y * y + z * z;             // same expression as passing kernel
    int cx = cell_of(x), cy = cell_of(y), cz = cell_of(z);
    int pos = atomicAdd(&g_cellCur[b][(cz * G + cy) * G + cx], 1);
    g_spos4[(size_t)b * Nk + pos] = make_float4(x, y, z, kk);
    g_sidx[(size_t)b * Nk + pos] = n;
}

__global__ __launch_bounds__(256) void scatterq_kernel(const float* __restrict__ q_pos) {
    int idx = blockIdx.x * 256 + threadIdx.x;     // 0 .. Bq*Sq-1
    int b = idx >> 10, s = idx & (Sq - 1);
    const float* qp = q_pos + (size_t)idx * 3;
    int cx = cell_of(qp[0]), cy = cell_of(qp[1]), cz = cell_of(qp[2]);
    int pos = atomicAdd(&g_qCur[b][(cz * G + cy) * G + cx], 1);
    g_qord[b * Sq + pos] = s;
}

// ---------------- row sums: feat[row,:] . csw + bias_sum ----------------
__global__ __launch_bounds__(256) void rowsum_kernel(const float* __restrict__ feat,
                                                     int rows, int mode) {
    __shared__ float sc[128];
    int t = threadIdx.x;
    if (t < 128) sc[t] = mode ? g_cswq[t] : g_cswk[t];
    __syncthreads();
    int row = blockIdx.x * 8 + (t >> 5);
    if (row >= rows) return;
    int lane = t & 31;
    float4 v = ((const float4*)feat)[(size_t)row * 32 + lane];
    float4 c = ((const float4*)sc)[lane];
    float d = v.x * c.x + v.y * c.y + v.z * c.z + v.w * c.w;
    #pragma unroll
    for (int o = 16; o; o >>= 1) d += __shfl_xor_sync(0xffffffffu, d, o);
    if (lane == 0) {
        float bs = mode ? g_consts[0] : g_consts[1];
        if (mode) g_qsum[row] = d + bs;
        else      g_ksum[row] = d + bs;
    }
}

// ---------------- grid KNN: 8 threads per query, cell-round-robin rings ----------
// d2 / key / threshold semantics byte-identical to the passing kernel.
// All group-level syncs use the 8-lane GROUP mask (gmask) — full-warp masks in
// the divergent ring loop caused the R12 deadlock.
__global__ __launch_bounds__(256) void knn_grid_kernel(const float* __restrict__ q_pos) {
    __shared__ ull sK[QPB3 * TPQ8 * KK];          // 32KB

    int t  = threadIdx.x;
    int qL = t >> 3;            // query within CTA (0..31)
    int sub = t & 7;            // thread within query group
    unsigned lane = t & 31;
    unsigned gmask = 0xFFu << (lane & ~7u);       // this group's 8 lanes
    int p  = blockIdx.x * QPB3 + qL;              // sorted query position (0..4095)
    int b  = p >> 10;
    int s  = g_qord[p];
    int gq = b * Sq + s;

    const float* qp = q_pos + (size_t)gq * 3;
    float qx = qp[0], qy = qp[1], qz = qp[2];
    float qq = qx * qx + qy * qy + qz * qz;       // same expression as passing kernel
    int cx = cell_of(qx), cy = cell_of(qy), cz = cell_of(qz);

    ull bK[KK];
    #pragma unroll
    for (int j = 0; j < KK; j++) bK[j] = 0xFFFFFFFFFFFFFFFFull;
    unsigned thr = 0xFFFFFFFFu;

    const float4* sp = g_spos4 + (size_t)b * Nk;
    const int*    si = g_sidx  + (size_t)b * Nk;
    const int*    cs = g_cellStart[b];
    const float h = 1.0f / (float)G;

#define EVALJ(J)                                                            \
    {                                                                       \
        float4 pt = sp[J];                                                  \
        float qk = fmaf(qz, pt.z, fmaf(qy, pt.y, qx * pt.x));               \
        float d2 = (qq - 2.f * qk) + pt.w;                                  \
        unsigned d2b = __float_as_uint(d2);                                 \
        if (d2b <= thr) {                                                   \
            int n = si[J];                                                  \
            ull key = ((ull)d2b << 32) | (ull)PERM(n);                      \
            if (key < bK[KK - 1]) {                                         \
                bK[KK - 1] = key;                                           \
                _Pragma("unroll")                                           \
                for (int jj = KK - 1; jj > 0; jj--) {                       \
                    if (bK[jj] < bK[jj - 1]) {                              \
                        ull tk = bK[jj]; bK[jj] = bK[jj - 1]; bK[jj - 1] = tk; \
                    } else break;                                           \
                }                                                           \
                thr = (unsigned)(bK[KK - 1] >> 32);                         \
            }                                                               \
        }                                                                   \
    }

#define SCANCELL(C)                                                         \
    {                                                                       \
        int j0 = cs[C], j1 = cs[(C) + 1];                                   \
        for (int j = j0; j < j1; j++) EVALJ(j)                              \
    }

    int ctr = 0;
    for (int r = 0; r < G; r++) {
        if (r >= 1) {
            // group-min of per-thread 16th-best d2 bits (upper bound on union 16th)
            unsigned m16 = (unsigned)(bK[KK - 1] >> 32);
            #pragma unroll
            for (int o = 4; o; o >>= 1) {
                unsigned v = __shfl_xor_sync(gmask, m16, o, 8);
                m16 = v < m16 ? v : m16;
            }
            float thrFg = __uint_as_float(m16);   // NaN while group not full
            int rIn = r - 1;
            float mg = 1e30f;
            if (cx - rIn > 0)     mg = fminf(mg, qx - (float)(cx - rIn) * h);
            if (cx + rIn < G - 1) mg = fminf(mg, (float)(cx + rIn + 1) * h - qx);
            if (cy - rIn > 0)     mg = fminf(mg, qy - (float)(cy - rIn) * h);
            if (cy + rIn < G - 1) mg = fminf(mg, (float)(cy + rIn + 1) * h - qy);
            if (cz - rIn > 0)     mg = fminf(mg, qz - (float)(cz - rIn) * h);
            if (cz + rIn < G - 1) mg = fminf(mg, (float)(cz + rIn + 1) * h - qz);
            if (mg > 0.f && (mg * mg - 1e-5f) > thrFg) break;  // uniform across group
        }
        int zlo = max(0, cz - r), zhi = min(G - 1, cz + r);
        for (int iz = zlo; iz <= zhi; iz++) {
            int adz = iz - cz; if (adz < 0) adz = -adz;
            int ylo = max(0, cy - r), yhi = min(G - 1, cy + r);
            for (int iy = ylo; iy <= yhi; iy++) {
                int ady = iy - cy; if (ady < 0) ady = -ady;
                int rowBase = (iz * G + iy) * G;
                if (adz == r || ady == r) {
                    int xlo = max(0, cx - r), xhi = min(G - 1, cx + r);
                    for (int ix = xlo; ix <= xhi; ix++) {
                        if (((ctr++) & 7) == sub) SCANCELL(rowBase + ix)
                    }
                } else {
                    if (cx - r >= 0)     { if (((ctr++) & 7) == sub) SCANCELL(rowBase + cx - r) }
                    if (cx + r <= G - 1) { if (((ctr++) & 7) == sub) SCANCELL(rowBase + cx + r) }
                }
            }
        }
    }
#undef SCANCELL
#undef EVALJ

    // dump sorted per-thread lists; 8-way merge by group leader
    {
        ull* seg = sK + (size_t)(qL * TPQ8 + sub) * KK;
        #pragma unroll
        for (int j = 0; j < KK; j++) seg[j] = bK[j];
    }
    __syncwarp(gmask);

    if (sub == 0) {
        const ull* lists = sK + (size_t)qL * TPQ8 * KK;
        int hp[TPQ8];
        #pragma unroll
        for (int u = 0; u < TPQ8; u++) hp[u] = 0;
        for (int r = 0; r < KK; r++) {
            ull bk = 0xFFFFFFFFFFFFFFFFull; int bu = 0;
            #pragma unroll
            for (int u = 0; u < TPQ8; u++) {
                int hh = hp[u];
                if (hh < KK) {
                    ull kv = lists[u * KK + hh];
                    if (kv < bk) { bk = kv; bu = u; }
                }
            }
            hp[bu]++;
            unsigned pm = (unsigned)(bk & 0x3FFFull);
            g_nidx[gq * KK + r] = (int)(((pm & 31u) << 9) | (pm >> 5));
        }
    }
}

// ---------------- PE-sum + scores + softmax(over k): 16 threads/query ----------
__global__ __launch_bounds__(256) void pe_kernel(const float* __restrict__ q_pos,
                                                 const float* __restrict__ k_pos,
                                                 const float* __restrict__ W1,
                                                 const float* __restrict__ b1) {
    constexpr int QPB = 16;
    __shared__ float sW1[384], sb1[128], sc2[128];

    int t  = threadIdx.x;
    int q  = t >> 4;
    int tq = t & 15;
    int b  = blockIdx.y;
    int s  = blockIdx.x * QPB + q;

    for (int i = t; i < 384; i += 256) sW1[i] = W1[i];
    if (t < 128) { sb1[t] = b1[t]; sc2[t] = g_csw2[t]; }
    __syncthreads();

    int gi = (b * Sq + s) * KK + tq;
    int myn = g_nidx[gi];

    const float* qp = q_pos + ((size_t)(b * Sq + s)) * 3;
    float qx = qp[0], qy = qp[1], qz = qp[2];
    const float* kp = k_pos + ((size_t)b * Nk + myn) * 3;
    float rx = qx - kp[0], ry = qy - kp[1], rz = qz - kp[2];
    float acc = 0.f;
    #pragma unroll 8
    for (int i = 0; i < 128; i++) {
        float hh = fmaf(sW1[i * 3], rx, fmaf(sW1[i * 3 + 1], ry, fmaf(sW1[i * 3 + 2], rz, sb1[i])));
        hh = fmaxf(hh, 0.f);
        acc = fmaf(sc2[i], hh, acc);
    }
    float score = g_qsum[b * Sq + s] - g_ksum[b * Nk + myn] + acc + g_consts[2];

    float m = score;
    #pragma unroll
    for (int o = 8; o; o >>= 1) m = fmaxf(m, __shfl_xor_sync(0xffffffffu, m, o, 16));
    float e = expf(score - m);
    float sum = e;
    #pragma unroll
    for (int o = 8; o; o >>= 1) sum += __shfl_xor_sync(0xffffffffu, sum, o, 16);
    g_attn[gi] = e / sum;
}

// ---------------- column sums of attn over S, per (b, slot j) ----------------
__global__ __launch_bounds__(256) void colsum_kernel() {
    int b = blockIdx.x >> 4, j = blockIdx.x & 15;
    float s = 0.f;
    for (int ss = threadIdx.x; ss < Sq; ss += 256) s += g_attn[(b * Sq + ss) * KK + j];
    #pragma unroll
    for (int o = 16; o; o >>= 1) s += __shfl_xor_sync(0xffffffffu, s, o);
    __shared__ float r[8];
    if ((threadIdx.x & 31) == 0) r[threadIdx.x >> 5] = s;
    __syncthreads();
    if (threadIdx.x == 0) {
        float tt = 0.f;
        #pragma unroll
        for (int w = 0; w < 8; w++) tt += r[w];
        g_acol[blockIdx.x] = tt;
    }
}

// ---------------- final: normalized gather-aggregate + single GEMM row ----------------
__global__ __launch_bounds__(128) void final_kernel(const float* __restrict__ k_feat,
                                                    const float* __restrict__ Wv,
                                                    const float* __restrict__ bv,
                                                    float* __restrict__ out) {
    constexpr int QPB2 = 32;
    extern __shared__ float sm[];
    float* WvS  = sm;                    // 128 rows x 132 stride (padded, conflict-free f4)
    float* sAgg = sm + 128 * 132;        // 128
    float* sA   = sAgg + 128;            // 16
    int*   sI   = (int*)(sA + 16);       // 16

    int t = threadIdx.x;
    for (int id = t; id < 128 * 128; id += 128) {
        int o = id >> 7, i = id & 127;
        WvS[o * 132 + i] = Wv[id];
    }
    float bvt = bv[t];

    for (int ql = 0; ql < QPB2; ql++) {
        int gq = blockIdx.x * QPB2 + ql;
        int b = gq >> 10;
        __syncthreads();
        if (t < 16) {
            float a = g_attn[gq * KK + t];
            a = a / (g_acol[b * KK + t] + 1e-6f);
            sA[t] = a;
            sI[t] = g_nidx[gq * KK + t];
        }
        __syncthreads();

        float agg = 0.f, asum = 0.f;
        #pragma unroll
        for (int j = 0; j < KK; j++) {
            float a = sA[j];
            asum += a;
            const float* vr = k_feat + ((size_t)(b * Nk) + sI[j]) * 128;
            agg = fmaf(a, vr[t], agg);
        }
        sAgg[t] = agg;
        __syncthreads();

        float a0 = 0.f, a1 = 0.f, a2 = 0.f, a3 = 0.f;
        const float4* wrow = (const float4*)(WvS + t * 132);
        const float4* aggv = (const float4*)sAgg;
        #pragma unroll
        for (int i4 = 0; i4 < 32; i4++) {
            float4 w = wrow[i4];
            float4 g = aggv[i4];
            a0 = fmaf(w.x, g.x, a0);
            a1 = fmaf(w.y, g.y, a1);
            a2 = fmaf(w.z, g.z, a2);
            a3 = fmaf(w.w, g.w, a3);
        }
        out[(size_t)gq * 128 + t] = ((a0 + a1) + (a2 + a3)) + asum * bvt;
    }
}

// ---------------- launch ----------------
extern "C" void kernel_launch(void* const* d_in, const int* in_sizes, int n_in,
                              void* d_out, int out_size) {
    const float* q_feat = (const float*)d_in[0];
    const float* k_feat = (const float*)d_in[1];
    const float* q_pos  = (const float*)d_in[2];
    const float* k_pos  = (const float*)d_in[3];
    const float* Wq     = (const float*)d_in[4];
    const float* bq     = (const float*)d_in[5];
    const float* Wk     = (const float*)d_in[6];
    const float* bk     = (const float*)d_in[7];
    const float* Wv     = (const float*)d_in[8];
    const float* bv     = (const float*)d_in[9];
    const float* W1     = (const float*)d_in[10];
    const float* b1     = (const float*)d_in[11];
    const float* W2     = (const float*)d_in[12];
    const float* b2     = (const float*)d_in[13];
    float* out = (float*)d_out;

    prep_kernel<<<1, 128>>>(Wq, bq, Wk, bk, W2, b2);
    zero_kernel<<<(2 * Bq * NC) / 256, 256>>>();
    count_kernel<<<(Bq * Nk) / 256, 256>>>(k_pos);
    countq_kernel<<<(Bq * Sq) / 256, 256>>>(q_pos);
    scan_kernel<<<2 * Bq, 1024>>>();
    scatter_kernel<<<(Bq * Nk) / 256, 256>>>(k_pos);
    scatterq_kernel<<<(Bq * Sq) / 256, 256>>>(q_pos);
    rowsum_kernel<<<(Bq * Nk) / 8, 256>>>(k_feat, Bq * Nk, 0);
    rowsum_kernel<<<(Bq * Sq) / 8, 256>>>(q_feat, Bq * Sq, 1);
    knn_grid_kernel<<<(Bq * Sq * TPQ8) / 256, 256>>>(q_pos);
    pe_kernel<<<dim3(Sq / 16, Bq), 256>>>(q_pos, k_pos, W1, b1);
    colsum_kernel<<<Bq * KK, 256>>>();

    int smemF = (128 * 132 + 128 + 16 + 16) * (int)sizeof(float);
    cudaFuncSetAttribute(final_kernel, cudaFuncAttributeMaxDynamicSharedMemorySize, smemF);
    final_kernel<<<(Bq * Sq) / 32, 128, smemF>>>(k_feat, Wv, bv, out);
}

// round 14
// speedup vs baseline: 3.6340x; 3.6340x over previous
#include <cuda_runtime.h>
#include <math.h>
#include <float.h>

#define Bq 4
#define Sq 1024
#define Nk 16384
#define KK 16
#define G  16
#define NC (G * G * G)   // 4096 cells

typedef unsigned long long ull;

// ---------------- scratch (device globals; no allocation allowed) ----------------
__device__ float g_cswq[128];
__device__ float g_cswk[128];
__device__ float g_csw2[128];
__device__ float g_consts[4];           // [0]=sum_bq, [1]=sum_bk, [2]=sum_b2
__device__ float g_qsum[Bq * Sq];
__device__ float g_ksum[Bq * Nk];
__device__ float g_attn[Bq * Sq * KK];
__device__ int   g_nidx[Bq * Sq * KK];
__device__ float g_acol[Bq * KK];
__device__ int    g_cellStart[Bq][NC + 1];
__device__ int    g_cellCur[Bq][NC];    // histogram, then running scatter offsets
__device__ float4 g_spos4[Bq * Nk];     // cell-sorted (x,y,z,kk)
__device__ int    g_sidx[Bq * Nk];      // original indices
__device__ int    g_qCur[Bq][NC];       // query histogram / running offsets
__device__ int    g_qord[Bq * Sq];      // cell-sorted query ids (per batch)

#define PERM(n) ((unsigned)((((n) & 511) << 5) | ((unsigned)(n) >> 9)))
#define FULLM 0xFFFFFFFFu

__device__ __forceinline__ int cell_of(float v) {
    int c = (int)(v * (float)G);
    return c < 0 ? 0 : (c > G - 1 ? G - 1 : c);
}

// ---------------- prep: column sums of Wq/Wk/W2, bias sums ----------------
__global__ void prep_kernel(const float* __restrict__ Wq, const float* __restrict__ bq,
                            const float* __restrict__ Wk, const float* __restrict__ bk,
                            const float* __restrict__ W2, const float* __restrict__ b2) {
    int i = threadIdx.x;  // 128 threads
    float sq = 0.f, sk = 0.f, s2 = 0.f;
    for (int o = 0; o < 128; o++) {
        sq += Wq[o * 128 + i];
        sk += Wk[o * 128 + i];
        s2 += W2[o * 128 + i];
    }
    g_cswq[i] = sq;
    g_cswk[i] = sk;
    g_csw2[i] = s2;

    float vq = bq[i], vk = bk[i], v2 = b2[i];
    #pragma unroll
    for (int o = 16; o; o >>= 1) {
        vq += __shfl_xor_sync(FULLM, vq, o);
        vk += __shfl_xor_sync(FULLM, vk, o);
        v2 += __shfl_xor_sync(FULLM, v2, o);
    }
    __shared__ float rb[3][4];
    if ((i & 31) == 0) {
        rb[0][i >> 5] = vq; rb[1][i >> 5] = vk; rb[2][i >> 5] = v2;
    }
    __syncthreads();
    if (i == 0) {
        g_consts[0] = rb[0][0] + rb[0][1] + rb[0][2] + rb[0][3];
        g_consts[1] = rb[1][0] + rb[1][1] + rb[1][2] + rb[1][3];
        g_consts[2] = rb[2][0] + rb[2][1] + rb[2][2] + rb[2][3];
    }
}

// ---------------- grid build ----------------
__global__ __launch_bounds__(256) void zero_kernel() {
    int i = blockIdx.x * 256 + threadIdx.x;       // 0 .. 2*Bq*NC-1
    if (i < Bq * NC) ((int*)g_cellCur)[i] = 0;
    else             ((int*)g_qCur)[i - Bq * NC] = 0;
}

__global__ __launch_bounds__(256) void count_kernel(const float* __restrict__ k_pos) {
    int idx = blockIdx.x * 256 + threadIdx.x;     // 0 .. Bq*Nk-1
    int b = idx >> 14;
    const float* kp = k_pos + (size_t)idx * 3;
    int cx = cell_of(kp[0]), cy = cell_of(kp[1]), cz = cell_of(kp[2]);
    atomicAdd(&g_cellCur[b][(cz * G + cy) * G + cx], 1);
}

__global__ __launch_bounds__(256) void countq_kernel(const float* __restrict__ q_pos) {
    int idx = blockIdx.x * 256 + threadIdx.x;     // 0 .. Bq*Sq-1
    int b = idx >> 10;
    const float* qp = q_pos + (size_t)idx * 3;
    int cx = cell_of(qp[0]), cy = cell_of(qp[1]), cz = cell_of(qp[2]);
    atomicAdd(&g_qCur[b][(cz * G + cy) * G + cx], 1);
}

// blockIdx.x in [0, 2*Bq): first Bq -> point grid (also writes cellStart),
// last Bq -> query grid (running offsets only).
__global__ __launch_bounds__(1024) void scan_kernel() {
    int bb = blockIdx.x, t = threadIdx.x;
    int isQ = bb >= Bq;
    int b = isQ ? bb - Bq : bb;
    int* cur = isQ ? g_qCur[b] : g_cellCur[b];
    __shared__ int part[1024];
    int base = t * 4;
    int c0 = cur[base], c1 = cur[base + 1], c2 = cur[base + 2], c3 = cur[base + 3];
    int s = c0 + c1 + c2 + c3;
    part[t] = s;
    __syncthreads();
    for (int o = 1; o < 1024; o <<= 1) {
        int v = (t >= o) ? part[t - o] : 0;
        __syncthreads();
        part[t] += v;
        __syncthreads();
    }
    int run = part[t] - s;
    if (!isQ) {
        g_cellStart[b][base] = run;     cur[base] = run;     run += c0;
        g_cellStart[b][base + 1] = run; cur[base + 1] = run; run += c1;
        g_cellStart[b][base + 2] = run; cur[base + 2] = run; run += c2;
        g_cellStart[b][base + 3] = run; cur[base + 3] = run; run += c3;
        if (t == 1023) g_cellStart[b][NC] = run;
    } else {
        cur[base] = run;     run += c0;
        cur[base + 1] = run; run += c1;
        cur[base + 2] = run; run += c2;
        cur[base + 3] = run;
    }
}

__global__ __launch_bounds__(256) void scatter_kernel(const float* __restrict__ k_pos) {
    int idx = blockIdx.x * 256 + threadIdx.x;     // 0 .. Bq*Nk-1
    int b = idx >> 14, n = idx & (Nk - 1);
    const float* kp = k_pos + (size_t)idx * 3;
    float x = kp[0], y = kp[1], z = kp[2];
    float kk = x * x + y * y + z * z;             // same expression as passing kernel
    int cx = cell_of(x), cy = cell_of(y), cz = cell_of(z);
    int pos = atomicAdd(&g_cellCur[b][(cz * G + cy) * G + cx], 1);
    g_spos4[(size_t)b * Nk + pos] = make_float4(x, y, z, kk);
    g_sidx[(size_t)b * Nk + pos] = n;
}

__global__ __launch_bounds__(256) void scatterq_kernel(const float* __restrict__ q_pos) {
    int idx = blockIdx.x * 256 + threadIdx.x;     // 0 .. Bq*Sq-1
    int b = idx >> 10, s = idx & (Sq - 1);
    const float* qp = q_pos + (size_t)idx * 3;
    int cx = cell_of(qp[0]), cy = cell_of(qp[1]), cz = cell_of(qp[2]);
    int pos = atomicAdd(&g_qCur[b][(cz * G + cy) * G + cx], 1);
    g_qord[b * Sq + pos] = s;
}

// ---------------- row sums: feat[row,:] . csw + bias_sum ----------------
__global__ __launch_bounds__(256) void rowsum_kernel(const float* __restrict__ feat,
                                                     int rows, int mode) {
    __shared__ float sc[128];
    int t = threadIdx.x;
    if (t < 128) sc[t] = mode ? g_cswq[t] : g_cswk[t];
    __syncthreads();
    int row = blockIdx.x * 8 + (t >> 5);
    if (row >= rows) return;
    int lane = t & 31;
    float4 v = ((const float4*)feat)[(size_t)row * 32 + lane];
    float4 c = ((const float4*)sc)[lane];
    float d = v.x * c.x + v.y * c.y + v.z * c.z + v.w * c.w;
    #pragma unroll
    for (int o = 16; o; o >>= 1) d += __shfl_xor_sync(FULLM, d, o);
    if (lane == 0) {
        float bs = mode ? g_consts[0] : g_consts[1];
        if (mode) g_qsum[row] = d + bs;
        else      g_ksum[row] = d + bs;
    }
}

// ---------------- grid KNN: ONE WARP per query ----------
// All 32 lanes evaluate points of each cell-row segment in parallel; candidates
// passing the (exact, union) threshold are serialized via ballot+shfl and
// inserted into a top-16 list replicated identically in every lane.
// d2 chain / key order / threshold / ring pruning semantics identical to the
// R11 passing kernel -> same selected top-16, bit for bit.
__global__ __launch_bounds__(256) void knn_warp_kernel(const float* __restrict__ q_pos) {
    int warpId = (blockIdx.x * 256 + threadIdx.x) >> 5;   // 0 .. Bq*Sq-1 (sorted pos)
    int lane = threadIdx.x & 31;
    int b = warpId >> 10;
    int s = g_qord[warpId];
    int gq = b * Sq + s;

    const float* qp = q_pos + (size_t)gq * 3;
    float qx = qp[0], qy = qp[1], qz = qp[2];
    float qq = qx * qx + qy * qy + qz * qz;       // same expression as passing kernel
    int cx = cell_of(qx), cy = cell_of(qy), cz = cell_of(qz);

    ull bK[KK];                                    // identical in all lanes
    #pragma unroll
    for (int j = 0; j < KK; j++) bK[j] = 0xFFFFFFFFFFFFFFFFull;
    unsigned thr = 0xFFFFFFFFu;                    // NaN bits until 16 filled

    const float4* sp = g_spos4 + (size_t)b * Nk;
    const int*    si = g_sidx  + (size_t)b * Nk;
    const int*    cs = g_cellStart[b];
    const float h = 1.0f / (float)G;

    // process one contiguous sorted-point segment [j0,j1), 32 points at a time
#define SEGMENT(J0, J1)                                                     \
    for (int base = (J0); base < (J1); base += 32) {                        \
        int j = base + lane;                                                \
        int act = j < (J1);                                                 \
        int jc = act ? j : (J1) - 1;                                        \
        float4 pt = sp[jc];                                                 \
        int n = si[jc];                                                     \
        float qk = fmaf(qz, pt.z, fmaf(qy, pt.y, qx * pt.x));               \
        float d2 = (qq - 2.f * qk) + pt.w;                                  \
        unsigned d2b = __float_as_uint(d2);                                 \
        unsigned m = __ballot_sync(FULLM, act && d2b <= thr);               \
        while (m) {                                                         \
            int src = __ffs(m) - 1; m &= m - 1;                             \
            unsigned cb = __shfl_sync(FULLM, d2b, src);                     \
            int cn = __shfl_sync(FULLM, n, src);                            \
            if (cb <= thr) {                                                \
                ull key = ((ull)cb << 32) | (ull)PERM(cn);                  \
                if (key < bK[KK - 1]) {                                     \
                    bK[KK - 1] = key;                                       \
                    _Pragma("unroll")                                       \
                    for (int jj = KK - 1; jj > 0; jj--) {                   \
                        if (bK[jj] < bK[jj - 1]) {                          \
                            ull tk = bK[jj]; bK[jj] = bK[jj - 1]; bK[jj - 1] = tk; \
                        } else break;                                       \
                    }                                                       \
                    thr = (unsigned)(bK[KK - 1] >> 32);                     \
                }                                                           \
            }                                                               \
        }                                                                   \
    }

    for (int r = 0; r < G; r++) {
        if (r >= 1) {
            float thrF = __uint_as_float(thr);    // NaN until 16 found
            int rIn = r - 1;
            float mg = 1e30f;
            if (cx - rIn > 0)     mg = fminf(mg, qx - (float)(cx - rIn) * h);
            if (cx + rIn < G - 1) mg = fminf(mg, (float)(cx + rIn + 1) * h - qx);
            if (cy - rIn > 0)     mg = fminf(mg, qy - (float)(cy - rIn) * h);
            if (cy + rIn < G - 1) mg = fminf(mg, (float)(cy + rIn + 1) * h - qy);
            if (cz - rIn > 0)     mg = fminf(mg, qz - (float)(cz - rIn) * h);
            if (cz + rIn < G - 1) mg = fminf(mg, (float)(cz + rIn + 1) * h - qz);
            if (mg > 0.f && (mg * mg - 1e-5f) > thrF) break;   // warp-uniform
        }
        int zlo = max(0, cz - r), zhi = min(G - 1, cz + r);
        for (int iz = zlo; iz <= zhi; iz++) {
            int adz = iz - cz; if (adz < 0) adz = -adz;
            int ylo = max(0, cy - r), yhi = min(G - 1, cy + r);
            for (int iy = ylo; iy <= yhi; iy++) {
                int ady = iy - cy; if (ady < 0) ady = -ady;
                int rowBase = (iz * G + iy) * G;
                if (adz == r || ady == r) {
                    int xlo = max(0, cx - r), xhi = min(G - 1, cx + r);
                    int j0 = cs[rowBase + xlo], j1 = cs[rowBase + xhi + 1];
                    SEGMENT(j0, j1)
                } else {
                    if (cx - r >= 0) {
                        int c = rowBase + cx - r;
                        int j0 = cs[c], j1 = cs[c + 1];
                        SEGMENT(j0, j1)
                    }
                    if (cx + r <= G - 1) {
                        int c = rowBase + cx + r;
                        int j0 = cs[c], j1 = cs[c + 1];
                        SEGMENT(j0, j1)
                    }
                }
            }
        }
    }
#undef SEGMENT

    if (lane == 0) {
        #pragma unroll
        for (int r2 = 0; r2 < KK; r2++) {
            unsigned pm = (unsigned)(bK[r2] & 0x3FFFull);
            g_nidx[gq * KK + r2] = (int)(((pm & 31u) << 9) | (pm >> 5));
        }
    }
}

// ---------------- PE-sum + scores + softmax(over k): 16 threads/query ----------
__global__ __launch_bounds__(256) void pe_kernel(const float* __restrict__ q_pos,
                                                 const float* __restrict__ k_pos,
                                                 const float* __restrict__ W1,
                                                 const float* __restrict__ b1) {
    constexpr int QPB = 16;
    __shared__ float sW1[384], sb1[128], sc2[128];

    int t  = threadIdx.x;
    int q  = t >> 4;
    int tq = t & 15;
    int b  = blockIdx.y;
    int s  = blockIdx.x * QPB + q;

    for (int i = t; i < 384; i += 256) sW1[i] = W1[i];
    if (t < 128) { sb1[t] = b1[t]; sc2[t] = g_csw2[t]; }
    __syncthreads();

    int gi = (b * Sq + s) * KK + tq;
    int myn = g_nidx[gi];

    const float* qp = q_pos + ((size_t)(b * Sq + s)) * 3;
    float qx = qp[0], qy = qp[1], qz = qp[2];
    const float* kp = k_pos + ((size_t)b * Nk + myn) * 3;
    float rx = qx - kp[0], ry = qy - kp[1], rz = qz - kp[2];
    float acc = 0.f;
    #pragma unroll 8
    for (int i = 0; i < 128; i++) {
        float hh = fmaf(sW1[i * 3], rx, fmaf(sW1[i * 3 + 1], ry, fmaf(sW1[i * 3 + 2], rz, sb1[i])));
        hh = fmaxf(hh, 0.f);
        acc = fmaf(sc2[i], hh, acc);
    }
    float score = g_qsum[b * Sq + s] - g_ksum[b * Nk + myn] + acc + g_consts[2];

    float m = score;
    #pragma unroll
    for (int o = 8; o; o >>= 1) m = fmaxf(m, __shfl_xor_sync(FULLM, m, o, 16));
    float e = expf(score - m);
    float sum = e;
    #pragma unroll
    for (int o = 8; o; o >>= 1) sum += __shfl_xor_sync(FULLM, sum, o, 16);
    g_attn[gi] = e / sum;
}

// ---------------- column sums of attn over S, per (b, slot j) ----------------
__global__ __launch_bounds__(256) void colsum_kernel() {
    int b = blockIdx.x >> 4, j = blockIdx.x & 15;
    float s = 0.f;
    for (int ss = threadIdx.x; ss < Sq; ss += 256) s += g_attn[(b * Sq + ss) * KK + j];
    #pragma unroll
    for (int o = 16; o; o >>= 1) s += __shfl_xor_sync(FULLM, s, o);
    __shared__ float r[8];
    if ((threadIdx.x & 31) == 0) r[threadIdx.x >> 5] = s;
    __syncthreads();
    if (threadIdx.x == 0) {
        float tt = 0.f;
        #pragma unroll
        for (int w = 0; w < 8; w++) tt += r[w];
        g_acol[blockIdx.x] = tt;
    }
}

// ---------------- final: normalized gather-aggregate + single GEMM row ----------------
__global__ __launch_bounds__(128) void final_kernel(const float* __restrict__ k_feat,
                                                    const float* __restrict__ Wv,
                                                    const float* __restrict__ bv,
                                                    float* __restrict__ out) {
    constexpr int QPB2 = 32;
    extern __shared__ float sm[];
    float* WvS  = sm;                    // 128 rows x 132 stride (padded, conflict-free f4)
    float* sAgg = sm + 128 * 132;        // 128
    float* sA   = sAgg + 128;            // 16
    int*   sI   = (int*)(sA + 16);       // 16

    int t = threadIdx.x;
    for (int id = t; id < 128 * 128; id += 128) {
        int o = id >> 7, i = id & 127;
        WvS[o * 132 + i] = Wv[id];
    }
    float bvt = bv[t];

    for (int ql = 0; ql < QPB2; ql++) {
        int gq = blockIdx.x * QPB2 + ql;
        int b = gq >> 10;
        __syncthreads();
        if (t < 16) {
            float a = g_attn[gq * KK + t];
            a = a / (g_acol[b * KK + t] + 1e-6f);
            sA[t] = a;
            sI[t] = g_nidx[gq * KK + t];
        }
        __syncthreads();

        float agg = 0.f, asum = 0.f;
        #pragma unroll
        for (int j = 0; j < KK; j++) {
            float a = sA[j];
            asum += a;
            const float* vr = k_feat + ((size_t)(b * Nk) + sI[j]) * 128;
            agg = fmaf(a, vr[t], agg);
        }
        sAgg[t] = agg;
        __syncthreads();

        float a0 = 0.f, a1 = 0.f, a2 = 0.f, a3 = 0.f;
        const float4* wrow = (const float4*)(WvS + t * 132);
        const float4* aggv = (const float4*)sAgg;
        #pragma unroll
        for (int i4 = 0; i4 < 32; i4++) {
            float4 w = wrow[i4];
            float4 g = aggv[i4];
            a0 = fmaf(w.x, g.x, a0);
            a1 = fmaf(w.y, g.y, a1);
            a2 = fmaf(w.z, g.z, a2);
            a3 = fmaf(w.w, g.w, a3);
        }
        out[(size_t)gq * 128 + t] = ((a0 + a1) + (a2 + a3)) + asum * bvt;
    }
}

// ---------------- launch ----------------
extern "C" void kernel_launch(void* const* d_in, const int* in_sizes, int n_in,
                              void* d_out, int out_size) {
    const float* q_feat = (const float*)d_in[0];
    const float* k_feat = (const float*)d_in[1];
    const float* q_pos  = (const float*)d_in[2];
    const float* k_pos  = (const float*)d_in[3];
    const float* Wq     = (const float*)d_in[4];
    const float* bq     = (const float*)d_in[5];
    const float* Wk     = (const float*)d_in[6];
    const float* bk     = (const float*)d_in[7];
    const float* Wv     = (const float*)d_in[8];
    const float* bv     = (const float*)d_in[9];
    const float* W1     = (const float*)d_in[10];
    const float* b1     = (const float*)d_in[11];
    const float* W2     = (const float*)d_in[12];
    const float* b2     = (const float*)d_in[13];
    float* out = (float*)d_out;

    prep_kernel<<<1, 128>>>(Wq, bq, Wk, bk, W2, b2);
    zero_kernel<<<(2 * Bq * NC) / 256, 256>>>();
    count_kernel<<<(Bq * Nk) / 256, 256>>>(k_pos);
    countq_kernel<<<(Bq * Sq) / 256, 256>>>(q_pos);
    scan_kernel<<<2 * Bq, 1024>>>();
    scatter_kernel<<<(Bq * Nk) / 256, 256>>>(k_pos);
    scatterq_kernel<<<(Bq * Sq) / 256, 256>>>(q_pos);
    rowsum_kernel<<<(Bq * Nk) / 8, 256>>>(k_feat, Bq * Nk, 0);
    rowsum_kernel<<<(Bq * Sq) / 8, 256>>>(q_feat, Bq * Sq, 1);
    knn_warp_kernel<<<(Bq * Sq * 32) / 256, 256>>>(q_pos);
    pe_kernel<<<dim3(Sq / 16, Bq), 256>>>(q_pos, k_pos, W1, b1);
    colsum_kernel<<<Bq * KK, 256>>>();

    int smemF = (128 * 132 + 128 + 16 + 16) * (int)sizeof(float);
    cudaFuncSetAttribute(final_kernel, cudaFuncAttributeMaxDynamicSharedMemorySize, smemF);
    final_kernel<<<(Bq * Sq) / 32, 128, smemF>>>(k_feat, Wv, bv, out);
}